// round 8
// baseline (speedup 1.0000x reference)
#include <cuda_runtime.h>
#include <math.h>

#define NN 10000
#define EE 320000
#define EA (EE + NN)
#define HID 256

// ---------------- scratch (static device memory; no allocs allowed) ----------
__device__ float g_deg[NN];
__device__ float g_asum[NN];
__device__ float g_loop[NN];
__device__ int   g_count[NN];
__device__ int   g_off[NN + 1];
__device__ int   g_cursor[NN];
__device__ int   g_csr_src[EA];
__device__ float g_csr_ea[EA];
__device__ float g_xl[NN * HID];
__device__ float g_xr[NN * HID];
__device__ float g_h[NN * HID];
__device__ float g_hn[NN * HID];
__device__ float g_p1[NN * 128];
__device__ float g_logits[NN * 4];
__device__ unsigned int g_maxenc;
__device__ float g_expsum;

// ---------------- helpers ----------------------------------------------------
__device__ __forceinline__ unsigned int fenc(float f) {
    unsigned int u = __float_as_uint(f);
    return (u & 0x80000000u) ? ~u : (u | 0x80000000u);
}
__device__ __forceinline__ float fdec(unsigned int e) {
    return (e & 0x80000000u) ? __uint_as_float(e & 0x7fffffffu)
                             : __uint_as_float(~e);
}
__device__ __forceinline__ float lrelu(float v) {
    return v > 0.f ? v : 0.2f * v;
}

// ---------------- init --------------------------------------------------------
__global__ void k_init() {
    int i = blockIdx.x * blockDim.x + threadIdx.x;
    if (i < NN) {
        g_deg[i] = 0.f; g_asum[i] = 0.f; g_count[i] = 0; g_cursor[i] = 0;
    }
    if (i == 0) { g_maxenc = 0u; g_expsum = 0.f; }
}

// ---------------- degree / loop attr -----------------------------------------
__global__ void k_degree(const int* __restrict__ ei, const float* __restrict__ ea) {
    int e = blockIdx.x * blockDim.x + threadIdx.x;
    if (e >= EE) return;
    int d = ei[EE + e];
    atomicAdd(&g_deg[d], 1.f);
    atomicAdd(&g_asum[d], ea[e]);
    atomicAdd(&g_count[d], 1);
}

__global__ void k_loopattr() {
    int n = blockIdx.x * blockDim.x + threadIdx.x;
    if (n >= NN) return;
    g_loop[n] = g_asum[n] / fmaxf(g_deg[n], 1.f);
}

// ---------------- single-block exclusive scan over (count+1) -----------------
__global__ void k_scan() {
    __shared__ int sm[1024];
    const int PER = (NN + 1023) / 1024;
    int tid = threadIdx.x;
    int base = tid * PER;
    int local[PER];
    int s = 0;
    #pragma unroll
    for (int i = 0; i < PER; ++i) {
        int idx = base + i;
        int v = (idx < NN) ? (g_count[idx] + 1) : 0;
        local[i] = s;
        s += v;
    }
    sm[tid] = s;
    __syncthreads();
    for (int off = 1; off < 1024; off <<= 1) {
        int v = (tid >= off) ? sm[tid - off] : 0;
        __syncthreads();
        sm[tid] += v;
        __syncthreads();
    }
    int prev = tid ? sm[tid - 1] : 0;
    #pragma unroll
    for (int i = 0; i < PER; ++i) {
        int idx = base + i;
        if (idx < NN) g_off[idx] = prev + local[i];
    }
    if (tid == 1023) g_off[NN] = sm[1023];
}

// ---------------- scatter to CSR ----------------------------------------------
__global__ void k_scatter(const int* __restrict__ ei, const float* __restrict__ ea) {
    int e = blockIdx.x * blockDim.x + threadIdx.x;
    if (e >= EA) return;
    int s, d; float a;
    if (e < EE) { s = ei[e]; d = ei[EE + e]; a = ea[e]; }
    else        { s = d = e - EE; a = g_loop[s]; }
    int pos = g_off[d] + atomicAdd(&g_cursor[d], 1);
    g_csr_src[pos] = s;
    g_csr_ea[pos]  = a;
}

// ---------------- conv1 input transform (K=4) ---------------------------------
__global__ void k_conv1_in(const float* __restrict__ x,
                           const float* __restrict__ Wl, const float* __restrict__ bl,
                           const float* __restrict__ Wr, const float* __restrict__ br) {
    int n = blockIdx.x;
    int c = threadIdx.x;
    __shared__ float xs[4];
    if (c < 4) xs[c] = x[n * 4 + c];
    __syncthreads();
    float sl = bl[c], sr = br[c];
    #pragma unroll
    for (int k = 0; k < 4; ++k) {
        sl += xs[k] * Wl[k * HID + c];
        sr += xs[k] * Wr[k * HID + c];
    }
    g_xl[n * HID + c] = sl;
    g_xr[n * HID + c] = sr;
}

// ---------------- edge aggregation: warp per dst node, online softmax --------
// HEADS=4 (reduce over 8 lanes) or HEADS=1 (reduce over 32 lanes).
template <int HEADS>
__global__ void k_edge_agg(const float* __restrict__ We, const float* __restrict__ att,
                           const float* __restrict__ bias, float* __restrict__ out) {
    int warp = (blockIdx.x * blockDim.x + threadIdx.x) >> 5;
    int lane = threadIdx.x & 31;
    if (warp >= NN) return;
    int n = warp;
    int c0 = lane * 8;

    float4 at0 = *(const float4*)(att + c0);
    float4 at1 = *(const float4*)(att + c0 + 4);
    float4 we0 = *(const float4*)(We + c0);
    float4 we1 = *(const float4*)(We + c0 + 4);
    const float4* xrp = (const float4*)(g_xr + (size_t)n * HID + c0);
    float4 xr0 = xrp[0], xr1 = xrp[1];

    float num[8];
    #pragma unroll
    for (int i = 0; i < 8; ++i) num[i] = 0.f;
    float m = -1e30f, den = 0.f;

    int beg = g_off[n], end = g_off[n + 1];
    for (int p = beg; p < end; ++p) {
        int s = g_csr_src[p];
        float ea = g_csr_ea[p];
        const float4* xsp = (const float4*)(g_xl + (size_t)s * HID + c0);
        float4 a = xsp[0], b = xsp[1];
        float part;
        part  = lrelu(a.x + xr0.x + ea * we0.x) * at0.x;
        part += lrelu(a.y + xr0.y + ea * we0.y) * at0.y;
        part += lrelu(a.z + xr0.z + ea * we0.z) * at0.z;
        part += lrelu(a.w + xr0.w + ea * we0.w) * at0.w;
        part += lrelu(b.x + xr1.x + ea * we1.x) * at1.x;
        part += lrelu(b.y + xr1.y + ea * we1.y) * at1.y;
        part += lrelu(b.z + xr1.z + ea * we1.z) * at1.z;
        part += lrelu(b.w + xr1.w + ea * we1.w) * at1.w;
        // reduce to the head's logit (8 lanes per head for H=4, 32 for H=1)
        part += __shfl_xor_sync(0xffffffffu, part, 1);
        part += __shfl_xor_sync(0xffffffffu, part, 2);
        part += __shfl_xor_sync(0xffffffffu, part, 4);
        if (HEADS == 1) {
            part += __shfl_xor_sync(0xffffffffu, part, 8);
            part += __shfl_xor_sync(0xffffffffu, part, 16);
        }
        float logit = part;
        float xs8[8] = {a.x, a.y, a.z, a.w, b.x, b.y, b.z, b.w};
        if (logit > m) {
            float sc = __expf(m - logit);
            den = den * sc + 1.f;
            #pragma unroll
            for (int i = 0; i < 8; ++i) num[i] = num[i] * sc + xs8[i];
            m = logit;
        } else {
            float w = __expf(logit - m);
            den += w;
            #pragma unroll
            for (int i = 0; i < 8; ++i) num[i] += w * xs8[i];
        }
    }
    float inv = 1.f / den;
    float4 bi0 = *(const float4*)(bias + c0);
    float4 bi1 = *(const float4*)(bias + c0 + 4);
    float4 o0, o1;
    o0.x = num[0] * inv + bi0.x; o0.y = num[1] * inv + bi0.y;
    o0.z = num[2] * inv + bi0.z; o0.w = num[3] * inv + bi0.w;
    o1.x = num[4] * inv + bi1.x; o1.y = num[5] * inv + bi1.y;
    o1.z = num[6] * inv + bi1.z; o1.w = num[7] * inv + bi1.w;
    float4* op = (float4*)(out + (size_t)n * HID + c0);
    op[0] = o0; op[1] = o1;
}

// ---------------- layernorm + relu (warp per node) ----------------------------
__global__ void k_ln_relu(const float* __restrict__ in, const float* __restrict__ g,
                          const float* __restrict__ b, float* __restrict__ out) {
    int warp = (blockIdx.x * blockDim.x + threadIdx.x) >> 5;
    int lane = threadIdx.x & 31;
    if (warp >= NN) return;
    int n = warp;
    int c0 = lane * 8;
    const float4* ip = (const float4*)(in + (size_t)n * HID + c0);
    float4 v0 = ip[0], v1 = ip[1];
    float s = v0.x + v0.y + v0.z + v0.w + v1.x + v1.y + v1.z + v1.w;
    #pragma unroll
    for (int o = 16; o > 0; o >>= 1) s += __shfl_xor_sync(0xffffffffu, s, o);
    float mu = s * (1.f / HID);
    float d0x = v0.x - mu, d0y = v0.y - mu, d0z = v0.z - mu, d0w = v0.w - mu;
    float d1x = v1.x - mu, d1y = v1.y - mu, d1z = v1.z - mu, d1w = v1.w - mu;
    float ss = d0x*d0x + d0y*d0y + d0z*d0z + d0w*d0w
             + d1x*d1x + d1y*d1y + d1z*d1z + d1w*d1w;
    #pragma unroll
    for (int o = 16; o > 0; o >>= 1) ss += __shfl_xor_sync(0xffffffffu, ss, o);
    float rstd = rsqrtf(ss * (1.f / HID) + 1e-5f);
    float4 gg0 = *(const float4*)(g + c0), gg1 = *(const float4*)(g + c0 + 4);
    float4 bb0 = *(const float4*)(b + c0), bb1 = *(const float4*)(b + c0 + 4);
    float4 o0, o1;
    o0.x = fmaxf(0.f, d0x * rstd * gg0.x + bb0.x);
    o0.y = fmaxf(0.f, d0y * rstd * gg0.y + bb0.y);
    o0.z = fmaxf(0.f, d0z * rstd * gg0.z + bb0.z);
    o0.w = fmaxf(0.f, d0w * rstd * gg0.w + bb0.w);
    o1.x = fmaxf(0.f, d1x * rstd * gg1.x + bb1.x);
    o1.y = fmaxf(0.f, d1y * rstd * gg1.y + bb1.y);
    o1.z = fmaxf(0.f, d1z * rstd * gg1.z + bb1.z);
    o1.w = fmaxf(0.f, d1w * rstd * gg1.w + bb1.w);
    float4* op = (float4*)(out + (size_t)n * HID + c0);
    op[0] = o0; op[1] = o1;
}

// ---------------- tiled SGEMM: C[M x Nc] = A[M x K] @ B[K x Nc] + bias --------
#define BM 128
#define BN 64
#define BK 16
template <bool RELU>
__global__ void k_sgemm(const float* __restrict__ A, const float* __restrict__ B,
                        const float* __restrict__ bias, float* __restrict__ C,
                        int M, int Nc, int K) {
    __shared__ float As[BK][BM];
    __shared__ float Bs[BK][BN];
    int row0 = blockIdx.y * BM;
    int col0 = blockIdx.x * BN;
    int tid = threadIdx.x;
    int tx = tid & 15, ty = tid >> 4;
    float acc[8][4];
    #pragma unroll
    for (int i = 0; i < 8; ++i)
        #pragma unroll
        for (int j = 0; j < 4; ++j) acc[i][j] = 0.f;

    for (int k0 = 0; k0 < K; k0 += BK) {
        #pragma unroll
        for (int u = 0; u < 2; ++u) {
            int f = tid + u * 256;
            int r = f >> 2, c4 = (f & 3) << 2;
            int grow = row0 + r;
            float4 v = make_float4(0.f, 0.f, 0.f, 0.f);
            if (grow < M) v = *(const float4*)(A + (size_t)grow * K + k0 + c4);
            As[c4 + 0][r] = v.x; As[c4 + 1][r] = v.y;
            As[c4 + 2][r] = v.z; As[c4 + 3][r] = v.w;
        }
        {
            int r = tid >> 4, c4 = (tid & 15) << 2;
            *(float4*)&Bs[r][c4] = *(const float4*)(B + (size_t)(k0 + r) * Nc + col0 + c4);
        }
        __syncthreads();
        #pragma unroll
        for (int kk = 0; kk < BK; ++kk) {
            float4 a0 = *(float4*)&As[kk][ty * 8];
            float4 a1 = *(float4*)&As[kk][ty * 8 + 4];
            float4 b0 = *(float4*)&Bs[kk][tx * 4];
            float av[8] = {a0.x, a0.y, a0.z, a0.w, a1.x, a1.y, a1.z, a1.w};
            float bv[4] = {b0.x, b0.y, b0.z, b0.w};
            #pragma unroll
            for (int i = 0; i < 8; ++i)
                #pragma unroll
                for (int j = 0; j < 4; ++j) acc[i][j] += av[i] * bv[j];
        }
        __syncthreads();
    }
    #pragma unroll
    for (int i = 0; i < 8; ++i) {
        int grow = row0 + ty * 8 + i;
        if (grow >= M) continue;
        #pragma unroll
        for (int j = 0; j < 4; ++j) {
            int gcol = col0 + tx * 4 + j;
            float v = acc[i][j] + bias[gcol];
            if (RELU) v = fmaxf(v, 0.f);
            C[(size_t)grow * Nc + gcol] = v;
        }
    }
}

// ---------------- p1 @ Wp2 + bp2 -> logits (warp per node) --------------------
__global__ void k_wp2(const float* __restrict__ Wp2, const float* __restrict__ bp2) {
    __shared__ float Ws[128 * 4];
    int tid = threadIdx.x;
    for (int i = tid; i < 128 * 4; i += blockDim.x) Ws[i] = Wp2[i];
    __syncthreads();
    int warp = (blockIdx.x * blockDim.x + tid) >> 5;
    int lane = tid & 31;
    if (warp >= NN) return;
    int n = warp;
    float o[4] = {0.f, 0.f, 0.f, 0.f};
    #pragma unroll
    for (int i = 0; i < 4; ++i) {
        int k = lane + 32 * i;
        float p = g_p1[(size_t)n * 128 + k];
        #pragma unroll
        for (int j = 0; j < 4; ++j) o[j] += p * Ws[k * 4 + j];
    }
    #pragma unroll
    for (int j = 0; j < 4; ++j) {
        #pragma unroll
        for (int off = 16; off > 0; off >>= 1)
            o[j] += __shfl_xor_sync(0xffffffffu, o[j], off);
    }
    if (lane == 0) {
        #pragma unroll
        for (int j = 0; j < 4; ++j) g_logits[n * 4 + j] = o[j] + bp2[j];
    }
}

// ---------------- global softmax over 40000 logits ----------------------------
__global__ void k_max() {
    __shared__ float sm[256];
    float m = -1e30f;
    for (int i = blockIdx.x * blockDim.x + threadIdx.x; i < NN * 4;
         i += gridDim.x * blockDim.x)
        m = fmaxf(m, g_logits[i]);
    sm[threadIdx.x] = m;
    __syncthreads();
    for (int o = 128; o > 0; o >>= 1) {
        if (threadIdx.x < o) sm[threadIdx.x] = fmaxf(sm[threadIdx.x], sm[threadIdx.x + o]);
        __syncthreads();
    }
    if (threadIdx.x == 0) atomicMax(&g_maxenc, fenc(sm[0]));
}

__global__ void k_expsum() {
    __shared__ float sm[256];
    float M = fdec(g_maxenc);
    float s = 0.f;
    for (int i = blockIdx.x * blockDim.x + threadIdx.x; i < NN * 4;
         i += gridDim.x * blockDim.x)
        s += expf(g_logits[i] - M);
    sm[threadIdx.x] = s;
    __syncthreads();
    for (int o = 128; o > 0; o >>= 1) {
        if (threadIdx.x < o) sm[threadIdx.x] += sm[threadIdx.x + o];
        __syncthreads();
    }
    if (threadIdx.x == 0) atomicAdd(&g_expsum, sm[0]);
}

__global__ void k_out(float* __restrict__ out) {
    int i = blockIdx.x * blockDim.x + threadIdx.x;
    if (i >= NN * 4) return;
    float M = fdec(g_maxenc);
    float inv = 1.f / g_expsum;
    out[i] = expf(g_logits[i] - M) * inv;
}

// ---------------- launch ------------------------------------------------------
// CRITICAL: __device__ symbols must NOT be passed directly as kernel args from
// host code (host sees the shadow symbol; ATS makes it silently read host
// memory). Fetch real device addresses via cudaGetSymbolAddress.
extern "C" void kernel_launch(void* const* d_in, const int* in_sizes, int n_in,
                              void* d_out, int out_size) {
    const float* x     = (const float*)d_in[0];
    const int*   ei    = (const int*)d_in[1];
    const float* eattr = (const float*)d_in[2];
    const float* Wl1 = (const float*)d_in[3];
    const float* bl1 = (const float*)d_in[4];
    const float* Wr1 = (const float*)d_in[5];
    const float* br1 = (const float*)d_in[6];
    const float* We1 = (const float*)d_in[7];
    const float* att1 = (const float*)d_in[8];
    const float* bias1 = (const float*)d_in[9];
    const float* g1  = (const float*)d_in[10];
    const float* be1 = (const float*)d_in[11];
    const float* Wl2 = (const float*)d_in[12];
    const float* bl2 = (const float*)d_in[13];
    const float* Wr2 = (const float*)d_in[14];
    const float* br2 = (const float*)d_in[15];
    const float* We2 = (const float*)d_in[16];
    const float* att2 = (const float*)d_in[17];
    const float* bias2 = (const float*)d_in[18];
    const float* g2  = (const float*)d_in[19];
    const float* be2 = (const float*)d_in[20];
    const float* Wp1 = (const float*)d_in[21];
    const float* bp1 = (const float*)d_in[22];
    const float* Wp2 = (const float*)d_in[23];
    const float* bp2 = (const float*)d_in[24];
    float* out = (float*)d_out;

    // real device addresses of scratch buffers
    void* pv;
    float *xl, *xr, *h, *hn, *p1;
    cudaGetSymbolAddress(&pv, g_xl);  xl = (float*)pv;
    cudaGetSymbolAddress(&pv, g_xr);  xr = (float*)pv;
    cudaGetSymbolAddress(&pv, g_h);   h  = (float*)pv;
    cudaGetSymbolAddress(&pv, g_hn);  hn = (float*)pv;
    cudaGetSymbolAddress(&pv, g_p1);  p1 = (float*)pv;

    // preprocessing
    k_init<<<(NN + 255) / 256, 256>>>();
    k_degree<<<(EE + 255) / 256, 256>>>(ei, eattr);
    k_loopattr<<<(NN + 255) / 256, 256>>>();
    k_scan<<<1, 1024>>>();
    k_scatter<<<(EA + 255) / 256, 256>>>(ei, eattr);

    // conv1 (H=4, C=64): writes device g_xl/g_xr internally
    k_conv1_in<<<NN, 256>>>(x, Wl1, bl1, Wr1, br1);
    k_edge_agg<4><<<(NN * 32 + 255) / 256, 256>>>(We1, att1, bias1, h);
    k_ln_relu<<<(NN * 32 + 255) / 256, 256>>>(h, g1, be1, hn);

    // conv2 (H=1, C=256)
    dim3 gC2((HID + BN - 1) / BN, (NN + BM - 1) / BM);
    k_sgemm<false><<<gC2, 256>>>(hn, Wl2, bl2, xl, NN, HID, HID);
    k_sgemm<false><<<gC2, 256>>>(hn, Wr2, br2, xr, NN, HID, HID);
    k_edge_agg<1><<<(NN * 32 + 255) / 256, 256>>>(We2, att2, bias2, h);
    k_ln_relu<<<(NN * 32 + 255) / 256, 256>>>(h, g2, be2, hn);

    // policy head
    dim3 gP1((128 + BN - 1) / BN, (NN + BM - 1) / BM);
    k_sgemm<true><<<gP1, 256>>>(hn, Wp1, bp1, p1, NN, 128, HID);
    k_wp2<<<(NN * 32 + 255) / 256, 256>>>(Wp2, bp2);

    // global softmax
    k_max<<<64, 256>>>();
    k_expsum<<<64, 256>>>();
    k_out<<<(NN * 4 + 255) / 256, 256>>>(out);
}